// round 11
// baseline (speedup 1.0000x reference)
#include <cuda_runtime.h>
#include <cstdint>
#include <math.h>

#define BB   64
#define NN   1024
#define CCH  64
#define KK   16
#define NPTS (BB*NN)

typedef unsigned long long ull;

// ---------------- scratch (device globals; no allocation allowed) ----------------
__device__ float g_X1[NPTS*CCH];
__device__ float g_X2[NPTS*CCH];
__device__ float g_X3[NPTS*CCH];
__device__ float g_P [NPTS*CCH];
__device__ float g_V [NPTS*CCH];
__device__ int   g_IDX[NPTS*KK];
__device__ float g_SQ[NPTS];

// monotone float->uint mapping (ascending), valid for negatives too
__device__ __forceinline__ unsigned int f2mono(float d){
    unsigned int u = __float_as_uint(d);
    return (u & 0x80000000u) ? ~u : (u | 0x80000000u);
}

// ---------------- packed f32x2 helpers (Blackwell FFMA2; fp32-exact per lane) ----------------
__device__ __forceinline__ void fma2(ull &acc, ull a, ull b){
    asm("fma.rn.f32x2 %0, %1, %2, %0;" : "+l"(acc) : "l"(a), "l"(b));
}
__device__ __forceinline__ ull pack2(float lo, float hi){
    ull r; asm("mov.b64 %0, {%1, %2};" : "=l"(r) : "f"(lo), "f"(hi)); return r;
}
__device__ __forceinline__ ull bcast2(float x){
    ull r; asm("mov.b64 %0, {%1, %1};" : "=l"(r) : "f"(x)); return r;
}
__device__ __forceinline__ void unpack2(ull v, float &lo, float &hi){
    asm("mov.b64 {%0, %1}, %2;" : "=f"(lo), "=f"(hi) : "l"(v));
}

// ---------------- squared norms (C=64 layers) ----------------
__global__ __launch_bounds__(256) void sq_kernel(const float* __restrict__ X){
    int w    = (blockIdx.x*256 + threadIdx.x) >> 5;
    int lane = threadIdx.x & 31;
    if (w >= NPTS) return;
    float s = 0.f;
    for (int k = lane; k < CCH; k += 32){ float v = X[(size_t)w*CCH + k]; s += v*v; }
    #pragma unroll
    for (int off = 16; off; off >>= 1) s += __shfl_down_sync(0xffffffffu, s, off);
    if (lane == 0) g_SQ[w] = s;
}

// ---------------- fused kNN, layer 1 (C = 1) ----------------
__global__ __launch_bounds__(256) void knn1_kernel(const float* __restrict__ X){
    __shared__ float xs[NN];
    __shared__ float ss[NN];
    __shared__ unsigned long long cand[64][65];
    int b = blockIdx.y, i0 = blockIdx.x << 6, tid = threadIdx.x;
    const float* Xb = X + (size_t)b*NN;
    for (int t = tid; t < NN; t += 256){ float v = Xb[t]; xs[t] = v; ss[t] = v*v; }
    __syncthreads();

    int srow = tid & 63, q = tid >> 6;
    float xi = xs[i0 + srow];
    float si = ss[i0 + srow];

    unsigned long long keys[16];
    #pragma unroll
    for (int s = 0; s < 16; s++) keys[s] = 0xFFFFFFFFFFFFFFFFull;

    int jb = q << 8;
    #pragma unroll 4
    for (int c = 0; c < 256; c++){
        int j = jb + c;
        float p = __fmul_rn(xi, xs[j]);
        float d = __fmaf_rn(-2.f, p, __fadd_rn(si, ss[j]));
        unsigned long long key = ((unsigned long long)f2mono(d) << 32) | (unsigned)j;
        if (key < keys[15]){
            keys[15] = key;
            #pragma unroll
            for (int s = 15; s > 0; --s)
                if (keys[s] < keys[s-1]){ unsigned long long tt = keys[s]; keys[s] = keys[s-1]; keys[s-1] = tt; }
        }
    }
    #pragma unroll
    for (int s = 0; s < 16; s++) cand[srow][(q << 4) + s] = keys[s];
    __syncthreads();

    if (tid < 64){
        int p4[4] = {0,0,0,0};
        size_t ob = ((size_t)(b*NN + i0 + tid))*KK;
        #pragma unroll
        for (int r = 0; r < 16; r++){
            unsigned long long best = 0xFFFFFFFFFFFFFFFFull; int bq = 0;
            #pragma unroll
            for (int q2 = 0; q2 < 4; q2++){
                if (p4[q2] < 16){
                    unsigned long long v = cand[tid][(q2 << 4) + p4[q2]];
                    if (v < best){ best = v; bq = q2; }
                }
            }
            p4[bq]++;
            g_IDX[ob + r] = (int)(best & 0xFFFFFFFFu);
        }
    }
}

// ---------------- fused kNN, C = 64 (layers 2,3), packed-FMA 8x8 microkernel ----------------
// Block = 128-row i-panel of one batch; 8 j-tiles of 128 cols.
// smem (dynamic): AT[64][136] | BT[64][136] | DT[128][65];  cand overlays AT.
#define KNN_AT_OFF   0
#define KNN_BT_OFF   (64*136)
#define KNN_DT_OFF   (2*64*136)
#define KNN_SMEM_B   ((2*64*136 + 128*65)*4)   // 102912 bytes

__global__ __launch_bounds__(256, 2) void knnC8_kernel(const float* __restrict__ X){
    extern __shared__ float sm[];
    float* AT = sm + KNN_AT_OFF;
    float* BT = sm + KNN_BT_OFF;
    float* DT = sm + KNN_DT_OFF;
    ull*  cand = (ull*)sm;                      // overlays AT/BT, used after tiles

    int b = blockIdx.y, i0 = blockIdx.x << 7, tid = threadIdx.x;
    const float* Xb = X + ((size_t)b*NN)*CCH;

    // load i-panel (AT, k-major) and first j-tile (BT)
    for (int t = tid; t < 8192; t += 256){
        int r = t >> 6, k = t & 63;
        AT[k*136 + r] = Xb[(size_t)(i0 + r)*CCH + k];
        BT[k*136 + r] = Xb[(size_t)r*CCH + k];
    }
    __syncthreads();

    int rg = tid >> 4, cg = tid & 15;           // 16x16 thread grid
    int rg8 = rg << 3, cg8 = cg << 3;
    int srow = tid >> 1;                         // scan row
    int half = tid & 1;

    float si[8];
    #pragma unroll
    for (int r = 0; r < 8; r++) si[r] = g_SQ[b*NN + i0 + rg8 + r];

    ull keys[16];
    #pragma unroll
    for (int s = 0; s < 16; s++) keys[s] = 0xFFFFFFFFFFFFFFFFull;

    for (int jt = 0; jt < 8; jt++){
        // ---- GEMM 128x128 tile, 8x8 per thread, rows packed in f32x2 ----
        ull acc[4][8] = {};
        #pragma unroll 4
        for (int k = 0; k < 64; k++){
            const float* ar = &AT[k*136 + rg8];
            const float* wr = &BT[k*136 + cg8];
            float4 a0 = *(const float4*)ar;
            float4 a1 = *(const float4*)(ar + 4);
            float4 w0 = *(const float4*)wr;
            float4 w1 = *(const float4*)(wr + 4);
            ull ap[4] = { pack2(a0.x,a0.y), pack2(a0.z,a0.w),
                          pack2(a1.x,a1.y), pack2(a1.z,a1.w) };
            ull wb[8] = { bcast2(w0.x), bcast2(w0.y), bcast2(w0.z), bcast2(w0.w),
                          bcast2(w1.x), bcast2(w1.y), bcast2(w1.z), bcast2(w1.w) };
            #pragma unroll
            for (int p = 0; p < 4; p++)
                #pragma unroll
                for (int c = 0; c < 8; c++) fma2(acc[p][c], ap[p], wb[c]);
        }
        __syncthreads();   // all GEMM reads of BT/DT done

        // ---- epilogue chunk 0 (cols 0..63 of tile) + prefetch next BT ----
        if ((cg >> 3) == 0){
            #pragma unroll
            for (int c = 0; c < 8; c++){
                float sjc = g_SQ[b*NN + (jt << 7) + cg8 + c];
                int lc = cg8 + c;
                #pragma unroll
                for (int p = 0; p < 4; p++){
                    float vlo, vhi; unpack2(acc[p][c], vlo, vhi);
                    DT[(rg8 + 2*p    )*65 + lc] = si[2*p    ] + sjc - 2.f*vlo;
                    DT[(rg8 + 2*p + 1)*65 + lc] = si[2*p + 1] + sjc - 2.f*vhi;
                }
            }
        }
        if (jt < 7){
            int jn = (jt + 1) << 7;
            for (int t = tid; t < 8192; t += 256){
                int r = t >> 6, k = t & 63;
                BT[k*136 + r] = Xb[(size_t)(jn + r)*CCH + k];
            }
        }
        __syncthreads();

        // ---- scan chunk 0 ----
        {
            int jbase = (jt << 7);
            const float* drow = &DT[srow*65];
            #pragma unroll
            for (int c = 0; c < 32; c++){
                int lc = (c << 1) | half;
                float d = drow[lc];
                ull key = ((ull)f2mono(d) << 32) | (unsigned)(jbase + lc);
                if (key < keys[15]){
                    keys[15] = key;
                    #pragma unroll
                    for (int s = 15; s > 0; --s)
                        if (keys[s] < keys[s-1]){ ull tt = keys[s]; keys[s] = keys[s-1]; keys[s-1] = tt; }
                }
            }
        }
        __syncthreads();

        // ---- epilogue chunk 1 (cols 64..127) ----
        if ((cg >> 3) == 1){
            #pragma unroll
            for (int c = 0; c < 8; c++){
                float sjc = g_SQ[b*NN + (jt << 7) + cg8 + c];
                int lc = cg8 + c - 64;
                #pragma unroll
                for (int p = 0; p < 4; p++){
                    float vlo, vhi; unpack2(acc[p][c], vlo, vhi);
                    DT[(rg8 + 2*p    )*65 + lc] = si[2*p    ] + sjc - 2.f*vlo;
                    DT[(rg8 + 2*p + 1)*65 + lc] = si[2*p + 1] + sjc - 2.f*vhi;
                }
            }
        }
        __syncthreads();

        // ---- scan chunk 1 ----
        {
            int jbase = (jt << 7) + 64;
            const float* drow = &DT[srow*65];
            #pragma unroll
            for (int c = 0; c < 32; c++){
                int lc = (c << 1) | half;
                float d = drow[lc];
                ull key = ((ull)f2mono(d) << 32) | (unsigned)(jbase + lc);
                if (key < keys[15]){
                    keys[15] = key;
                    #pragma unroll
                    for (int s = 15; s > 0; --s)
                        if (keys[s] < keys[s-1]){ ull tt = keys[s]; keys[s] = keys[s-1]; keys[s-1] = tt; }
                }
            }
        }
        __syncthreads();
    }

    // ---- dump lists + per-row 2-way merge ----
    #pragma unroll
    for (int s = 0; s < 16; s++) cand[tid*17 + s] = keys[s];
    __syncthreads();

    if (tid < 128){
        const ull* A  = &cand[(2*tid    )*17];
        const ull* Bq = &cand[(2*tid + 1)*17];
        int pa = 0, pb = 0;
        size_t ob = ((size_t)(b*NN + i0 + tid))*KK;
        #pragma unroll
        for (int r = 0; r < 16; r++){
            ull va = (pa < 16) ? A[pa]  : 0xFFFFFFFFFFFFFFFFull;
            ull vb = (pb < 16) ? Bq[pb] : 0xFFFFFFFFFFFFFFFFull;
            if (va <= vb){ g_IDX[ob + r] = (int)(va & 0xFFFFFFFFu); pa++; }
            else         { g_IDX[ob + r] = (int)(vb & 0xFFFFFFFFu); pb++; }
        }
    }
}

// ---------------- per-point transforms: P = x@(W1a-W1b)+b1, V = x@W1b ----------------
__global__ __launch_bounds__(256) void pv_kernel(const float* __restrict__ X,
                                                 const float* __restrict__ W1,
                                                 const float* __restrict__ B1, int Cin){
    __shared__ float xs[4][64];
    int base = blockIdx.x << 2;
    for (int t = threadIdx.x; t < 4*Cin; t += 256)
        xs[t/Cin][t%Cin] = X[(size_t)(base + t/Cin)*Cin + (t % Cin)];
    __syncthreads();
    int lp = threadIdx.x >> 6, c = threadIdx.x & 63;
    float p = B1[c], v = 0.f;
    for (int k = 0; k < Cin; k++){
        float xk = xs[lp][k];
        float wa = W1[k*64 + c];
        float wb = W1[(Cin + k)*64 + c];
        v = fmaf(xk, wb, v);
        p = fmaf(xk, wa - wb, p);
    }
    g_P[(size_t)(base + lp)*64 + c] = p;
    g_V[(size_t)(base + lp)*64 + c] = v;
}

// ---------------- edge GEMM + max, packed-FMA 8x8 microkernel ----------------
// Block = 16 points = 256 edges x 64 channels; thread: 8 edges x 8 channels.
// smem (dynamic): HT[64][264] | W2s[64][68] | red[32][68] | sj[256]
#define EDG_HT_OFF   0
#define EDG_W2_OFF   (64*264)
#define EDG_RED_OFF  (64*264 + 64*68)
#define EDG_SJ_OFF   (64*264 + 64*68 + 32*68)
#define EDG_SMEM_B   ((64*264 + 64*68 + 32*68 + 256)*4)   // 94720 bytes

__global__ __launch_bounds__(256, 2) void edge8_kernel(const float* __restrict__ W2,
                                                       const float* __restrict__ B2,
                                                       float* __restrict__ Xout){
    extern __shared__ float sm[];
    float* HT  = sm + EDG_HT_OFF;
    float* W2s = sm + EDG_W2_OFF;
    float* red = sm + EDG_RED_OFF;
    int*   sj  = (int*)(sm + EDG_SJ_OFF);

    int tid  = threadIdx.x;
    int base = blockIdx.x << 4;                  // 16 points, one batch
    int b    = base >> 10;
    const float* Vb = g_V + (((size_t)b) << 10)*64;

    if (tid < 256) sj[tid] = g_IDX[(size_t)(base + (tid >> 4))*KK + (tid & 15)];
    for (int t = tid; t < 4096; t += 256){
        int k = t >> 6, c = t & 63;
        W2s[k*68 + c] = W2[k*64 + c];
    }
    __syncthreads();

    // build HT[k][e] = relu(P[point(e)][k] + V[sj[e]][k])
    for (int t = tid; t < 16384; t += 256){
        int e = t >> 6, k = t & 63;
        int p = e >> 4;
        float h = g_P[(size_t)(base + p)*64 + k] + Vb[(size_t)sj[e]*64 + k];
        HT[k*264 + e] = fmaxf(h, 0.f);
    }
    __syncthreads();

    int eg = tid >> 3, cg = tid & 7;             // 32x8 thread grid
    int eg8 = eg << 3, cg8 = cg << 3;

    ull acc[4][8] = {};
    #pragma unroll 4
    for (int k = 0; k < 64; k++){
        const float* ar = &HT [k*264 + eg8];
        const float* wr = &W2s[k*68  + cg8];
        float4 a0 = *(const float4*)ar;
        float4 a1 = *(const float4*)(ar + 4);
        float4 w0 = *(const float4*)wr;
        float4 w1 = *(const float4*)(wr + 4);
        ull ap[4] = { pack2(a0.x,a0.y), pack2(a0.z,a0.w),
                      pack2(a1.x,a1.y), pack2(a1.z,a1.w) };
        ull wb[8] = { bcast2(w0.x), bcast2(w0.y), bcast2(w0.z), bcast2(w0.w),
                      bcast2(w1.x), bcast2(w1.y), bcast2(w1.z), bcast2(w1.w) };
        #pragma unroll
        for (int p = 0; p < 4; p++)
            #pragma unroll
            for (int c = 0; c < 8; c++) fma2(acc[p][c], ap[p], wb[c]);
    }

    // per-thread max over its 8 edges (all within one point), per channel
    int p  = eg >> 1;       // point index within block (0..15)
    int hp = eg & 1;        // which half of the point's 16 edges
    #pragma unroll
    for (int c = 0; c < 8; c++){
        float l0,h0,l1,h1,l2,h2,l3,h3;
        unpack2(acc[0][c], l0, h0); unpack2(acc[1][c], l1, h1);
        unpack2(acc[2][c], l2, h2); unpack2(acc[3][c], l3, h3);
        float m = fmaxf(fmaxf(fmaxf(l0,h0), fmaxf(l1,h1)),
                        fmaxf(fmaxf(l2,h2), fmaxf(l3,h3)));
        red[((p << 1) | hp)*68 + cg8 + c] = m;
    }
    __syncthreads();

    // 1024 outputs: combine the two halves, add bias
    #pragma unroll
    for (int o = 0; o < 4; o++){
        int idx = tid + (o << 8);
        int pp = idx >> 6, c = idx & 63;
        float m = fmaxf(red[(pp << 1)*68 + c], red[((pp << 1) | 1)*68 + c]);
        Xout[(size_t)(base + pp)*64 + c] = m + B2[c];
    }
}

// ---------------- MLP head + log_softmax ----------------
__global__ __launch_bounds__(128) void head_kernel(const float* __restrict__ mw1, const float* __restrict__ mb1,
                                                   const float* __restrict__ mw2, const float* __restrict__ mb2,
                                                   const float* __restrict__ mw3, const float* __restrict__ mb3,
                                                   const float* __restrict__ mw4, const float* __restrict__ mb4,
                                                   float* __restrict__ out){
    __shared__ float in[192], h1[128], h2[64], h3[32], o2[2];
    int t = threadIdx.x;
    int p0 = blockIdx.x * 16;
    for (int p = p0; p < p0 + 16; p++){
        if (t < 64){
            in[t      ] = g_X1[(size_t)p*64 + t];
            in[t +  64] = g_X2[(size_t)p*64 + t];
            in[t + 128] = g_X3[(size_t)p*64 + t];
        }
        __syncthreads();
        {
            float a = mb1[t];
            #pragma unroll 8
            for (int k = 0; k < 192; k++) a = fmaf(in[k], mw1[k*128 + t], a);
            h1[t] = fmaxf(a, 0.f);
        }
        __syncthreads();
        if (t < 64){
            float a = mb2[t];
            #pragma unroll 8
            for (int k = 0; k < 128; k++) a = fmaf(h1[k], mw2[k*64 + t], a);
            h2[t] = fmaxf(a, 0.f);
        }
        __syncthreads();
        if (t < 32){
            float a = mb3[t];
            #pragma unroll 8
            for (int k = 0; k < 64; k++) a = fmaf(h2[k], mw3[k*32 + t], a);
            h3[t] = fmaxf(a, 0.f);
        }
        __syncthreads();
        if (t < 2){
            float a = mb4[t];
            #pragma unroll
            for (int k = 0; k < 32; k++) a = fmaf(h3[k], mw4[k*2 + t], a);
            o2[t] = a;
        }
        __syncthreads();
        if (t < 2){
            float m   = fmaxf(o2[0], o2[1]);
            float lse = m + logf(expf(o2[0] - m) + expf(o2[1] - m));
            out[(size_t)p*2 + t] = o2[t] - lse;
        }
        __syncthreads();
    }
}

// ---------------- launch ----------------
extern "C" void kernel_launch(void* const* d_in, const int* in_sizes, int n_in,
                              void* d_out, int out_size){
    const float* x    = (const float*)d_in[0];
    const float* c1w1 = (const float*)d_in[1];
    const float* c1b1 = (const float*)d_in[2];
    const float* c1w2 = (const float*)d_in[3];
    const float* c1b2 = (const float*)d_in[4];
    const float* c2w1 = (const float*)d_in[5];
    const float* c2b1 = (const float*)d_in[6];
    const float* c2w2 = (const float*)d_in[7];
    const float* c2b2 = (const float*)d_in[8];
    const float* c3w1 = (const float*)d_in[9];
    const float* c3b1 = (const float*)d_in[10];
    const float* c3w2 = (const float*)d_in[11];
    const float* c3b2 = (const float*)d_in[12];
    const float* mw1  = (const float*)d_in[13];
    const float* mb1  = (const float*)d_in[14];
    const float* mw2  = (const float*)d_in[15];
    const float* mb2  = (const float*)d_in[16];
    const float* mw3  = (const float*)d_in[17];
    const float* mb3  = (const float*)d_in[18];
    const float* mw4  = (const float*)d_in[19];
    const float* mb4  = (const float*)d_in[20];

    void *pX1, *pX2, *pX3;
    cudaGetSymbolAddress(&pX1, g_X1);
    cudaGetSymbolAddress(&pX2, g_X2);
    cudaGetSymbolAddress(&pX3, g_X3);
    float* X1 = (float*)pX1;
    float* X2 = (float*)pX2;
    float* X3 = (float*)pX3;

    cudaFuncSetAttribute(knnC8_kernel, cudaFuncAttributeMaxDynamicSharedMemorySize, KNN_SMEM_B);
    cudaFuncSetAttribute(edge8_kernel, cudaFuncAttributeMaxDynamicSharedMemorySize, EDG_SMEM_B);

    // ---- layer 1 (Cin = 1): fused knn ----
    knn1_kernel<<<dim3(16, BB), 256>>>(x);
    pv_kernel  <<<16384, 256>>>(x, c1w1, c1b1, 1);
    edge8_kernel<<<4096, 256, EDG_SMEM_B>>>(c1w2, c1b2, X1);

    // ---- layer 2 (Cin = 64) ----
    sq_kernel  <<<8192, 256>>>(X1);
    knnC8_kernel<<<dim3(8, BB), 256, KNN_SMEM_B>>>(X1);
    pv_kernel  <<<16384, 256>>>(X1, c2w1, c2b1, 64);
    edge8_kernel<<<4096, 256, EDG_SMEM_B>>>(c2w2, c2b2, X2);

    // ---- layer 3 (Cin = 64) ----
    sq_kernel  <<<8192, 256>>>(X2);
    knnC8_kernel<<<dim3(8, BB), 256, KNN_SMEM_B>>>(X2);
    pv_kernel  <<<16384, 256>>>(X2, c3w1, c3b1, 64);
    edge8_kernel<<<4096, 256, EDG_SMEM_B>>>(c3w2, c3b2, X3);

    // ---- head ----
    head_kernel<<<4096, 128>>>(mw1, mb1, mw2, mb2, mw3, mb3, mw4, mb4, (float*)d_out);
}

// round 13
// speedup vs baseline: 1.2382x; 1.2382x over previous
#include <cuda_runtime.h>
#include <cstdint>
#include <math.h>

#define BB   64
#define NN   1024
#define CCH  64
#define KK   16
#define NPTS (BB*NN)

typedef unsigned long long ull;

// ---------------- scratch (device globals; no allocation allowed) ----------------
__device__ float g_X1[NPTS*CCH];
__device__ float g_X2[NPTS*CCH];
__device__ float g_X3[NPTS*CCH];
__device__ float g_P [NPTS*CCH];
__device__ float g_V [NPTS*CCH];
__device__ float g_H1[NPTS*128];
__device__ int   g_IDX[NPTS*KK];
__device__ float g_SQ[NPTS];

// monotone float->uint mapping (ascending), valid for negatives too
__device__ __forceinline__ unsigned int f2mono(float d){
    unsigned int u = __float_as_uint(d);
    return (u & 0x80000000u) ? ~u : (u | 0x80000000u);
}

// ---------------- squared norms (C=64 layers) ----------------
__global__ __launch_bounds__(256) void sq_kernel(const float* __restrict__ X){
    int w    = (blockIdx.x*256 + threadIdx.x) >> 5;
    int lane = threadIdx.x & 31;
    if (w >= NPTS) return;
    float s = 0.f;
    for (int k = lane; k < CCH; k += 32){ float v = X[(size_t)w*CCH + k]; s += v*v; }
    #pragma unroll
    for (int off = 16; off; off >>= 1) s += __shfl_down_sync(0xffffffffu, s, off);
    if (lane == 0) g_SQ[w] = s;
}

// ---------------- fused kNN, layer 1 (C = 1) ----------------
__global__ __launch_bounds__(256) void knn1_kernel(const float* __restrict__ X){
    __shared__ float xs[NN];
    __shared__ float ss[NN];
    __shared__ unsigned long long cand[64][65];
    int b = blockIdx.y, i0 = blockIdx.x << 6, tid = threadIdx.x;
    const float* Xb = X + (size_t)b*NN;
    for (int t = tid; t < NN; t += 256){ float v = Xb[t]; xs[t] = v; ss[t] = v*v; }
    __syncthreads();

    int srow = tid & 63, q = tid >> 6;
    float xi = xs[i0 + srow];
    float si = ss[i0 + srow];

    unsigned long long keys[16];
    #pragma unroll
    for (int s = 0; s < 16; s++) keys[s] = 0xFFFFFFFFFFFFFFFFull;
    unsigned thr = 0xFFFFFFFFu;

    int jb = q << 8;
    #pragma unroll 4
    for (int c = 0; c < 256; c++){
        int j = jb + c;
        float p = __fmul_rn(xi, xs[j]);
        float d = __fmaf_rn(-2.f, p, __fadd_rn(si, ss[j]));
        unsigned mono = f2mono(d);
        // j strictly ascending per thread => mono == hi(keys[15]) can never insert
        if (mono < thr){
            ull key = ((ull)mono << 32) | (unsigned)j;
            keys[15] = key;
            #pragma unroll
            for (int s = 15; s > 0; --s)
                if (keys[s] < keys[s-1]){ ull tt = keys[s]; keys[s] = keys[s-1]; keys[s-1] = tt; }
            thr = (unsigned)(keys[15] >> 32);
        }
    }
    #pragma unroll
    for (int s = 0; s < 16; s++) cand[srow][(q << 4) + s] = keys[s];
    __syncthreads();

    if (tid < 64){
        int p4[4] = {0,0,0,0};
        size_t ob = ((size_t)(b*NN + i0 + tid))*KK;
        #pragma unroll
        for (int r = 0; r < 16; r++){
            unsigned long long best = 0xFFFFFFFFFFFFFFFFull; int bq = 0;
            #pragma unroll
            for (int q2 = 0; q2 < 4; q2++){
                if (p4[q2] < 16){
                    unsigned long long v = cand[tid][(q2 << 4) + p4[q2]];
                    if (v < best){ best = v; bq = q2; }
                }
            }
            p4[bq]++;
            g_IDX[ob + r] = (int)(best & 0xFFFFFFFFu);
        }
    }
}

// ---------------- fused kNN, C = 64 (layers 2,3) — R8 shape (4x4 microkernel) ----------------
struct KnnSmem {
    union {
        struct { float AT[64][68]; float BT[64][68]; } g;   // 34816 B
        unsigned long long cand[64][65];                    // 33280 B
    };
    float DT[64][65];
};

__global__ __launch_bounds__(256) void knnC_kernel(const float* __restrict__ X){
    __shared__ KnnSmem s;
    int b = blockIdx.y, i0 = blockIdx.x << 6, tid = threadIdx.x;
    const float* Xb = X + ((size_t)b*NN)*CCH;

    for (int t = tid; t < 4096; t += 256){
        int r = t >> 6, k = t & 63;
        s.g.AT[k][r] = Xb[(size_t)(i0 + r)*CCH + k];
        s.g.BT[k][r] = Xb[(size_t)r*CCH + k];
    }
    __syncthreads();

    int er = tid >> 4, cc = tid & 15;
    int srow = tid & 63, q = tid >> 6;
    float si4[4];
    #pragma unroll
    for (int r = 0; r < 4; r++) si4[r] = g_SQ[b*NN + i0 + (er << 2) + r];

    unsigned long long keys[16];
    #pragma unroll
    for (int ss = 0; ss < 16; ss++) keys[ss] = 0xFFFFFFFFFFFFFFFFull;
    unsigned thr = 0xFFFFFFFFu;

    for (int jt = 0; jt < 16; jt++){
        // ---- GEMM tile: acc = AT^T * BT ----
        float acc[4][4] = {};
        #pragma unroll 8
        for (int k = 0; k < 64; k++){
            float4 a = *(const float4*)&s.g.AT[k][er << 2];
            float4 w = *(const float4*)&s.g.BT[k][cc << 2];
            acc[0][0]+=a.x*w.x; acc[0][1]+=a.x*w.y; acc[0][2]+=a.x*w.z; acc[0][3]+=a.x*w.w;
            acc[1][0]+=a.y*w.x; acc[1][1]+=a.y*w.y; acc[1][2]+=a.y*w.z; acc[1][3]+=a.y*w.w;
            acc[2][0]+=a.z*w.x; acc[2][1]+=a.z*w.y; acc[2][2]+=a.z*w.z; acc[2][3]+=a.z*w.w;
            acc[3][0]+=a.w*w.x; acc[3][1]+=a.w*w.y; acc[3][2]+=a.w*w.z; acc[3][3]+=a.w*w.w;
        }
        float sj4[4];
        #pragma unroll
        for (int c = 0; c < 4; c++) sj4[c] = g_SQ[b*NN + (jt << 6) + (cc << 2) + c];
        #pragma unroll
        for (int r = 0; r < 4; r++){
            #pragma unroll
            for (int c = 0; c < 4; c++)
                s.DT[(er << 2) + r][(cc << 2) + c] = si4[r] + sj4[c] - 2.f*acc[r][c];
        }
        __syncthreads();

        // ---- prefetch next BT tile (doesn't touch DT) ----
        if (jt < 15){
            int jn = (jt + 1) << 6;
            for (int t = tid; t < 4096; t += 256){
                int r = t >> 6, k = t & 63;
                s.g.BT[k][r] = Xb[(size_t)(jn + r)*CCH + k];
            }
        }

        // ---- top-16 scan of this tile (16 values per thread, j ascending) ----
        #pragma unroll
        for (int c = 0; c < 16; c++){
            int jl = (q << 4) + c;
            float d = s.DT[srow][jl];
            unsigned mono = f2mono(d);
            if (mono < thr){
                ull key = ((ull)mono << 32) | (unsigned)((jt << 6) + jl);
                keys[15] = key;
                #pragma unroll
                for (int ss = 15; ss > 0; --ss)
                    if (keys[ss] < keys[ss-1]){ ull tt = keys[ss]; keys[ss] = keys[ss-1]; keys[ss-1] = tt; }
                thr = (unsigned)(keys[15] >> 32);
            }
        }
        __syncthreads();
    }

    // ---- dump + 4-way merge per row ----
    #pragma unroll
    for (int ss = 0; ss < 16; ss++) s.cand[srow][(q << 4) + ss] = keys[ss];
    __syncthreads();

    if (tid < 64){
        int p4[4] = {0,0,0,0};
        size_t ob = ((size_t)(b*NN + i0 + tid))*KK;
        #pragma unroll
        for (int r = 0; r < 16; r++){
            unsigned long long best = 0xFFFFFFFFFFFFFFFFull; int bq = 0;
            #pragma unroll
            for (int q2 = 0; q2 < 4; q2++){
                if (p4[q2] < 16){
                    unsigned long long v = s.cand[tid][(q2 << 4) + p4[q2]];
                    if (v < best){ best = v; bq = q2; }
                }
            }
            p4[bq]++;
            g_IDX[ob + r] = (int)(best & 0xFFFFFFFFu);
        }
    }
}

// ---------------- per-point transforms: P = x@(W1a-W1b)+b1, V = x@W1b ----------------
__global__ __launch_bounds__(256) void pv_kernel(const float* __restrict__ X,
                                                 const float* __restrict__ W1,
                                                 const float* __restrict__ B1, int Cin){
    __shared__ float xs[4][64];
    int base = blockIdx.x << 2;
    for (int t = threadIdx.x; t < 4*Cin; t += 256)
        xs[t/Cin][t%Cin] = X[(size_t)(base + t/Cin)*Cin + (t % Cin)];
    __syncthreads();
    int lp = threadIdx.x >> 6, c = threadIdx.x & 63;
    float p = B1[c], v = 0.f;
    for (int k = 0; k < Cin; k++){
        float xk = xs[lp][k];
        float wa = W1[k*64 + c];
        float wb = W1[(Cin + k)*64 + c];
        v = fmaf(xk, wb, v);
        p = fmaf(xk, wa - wb, p);
    }
    g_P[(size_t)(base + lp)*64 + c] = p;
    g_V[(size_t)(base + lp)*64 + c] = v;
}

// ---------------- edge GEMM + max (R8 shape) ----------------
__global__ __launch_bounds__(256) void edge_kernel(const float* __restrict__ W2,
                                                   const float* __restrict__ B2,
                                                   float* __restrict__ Xout){
    __shared__ __align__(16) float HT [64][68];
    __shared__ __align__(16) float W2s[64][68];
    __shared__ __align__(16) float red[16][68];
    __shared__ int sj[64];
    int tid  = threadIdx.x;
    int base = blockIdx.x << 2;
    int b    = base >> 10;
    const float* Vb = g_V + (((size_t)b) << 10)*64;

    if (tid < 64) sj[tid] = g_IDX[(base + (tid >> 4))*KK + (tid & 15)];
    for (int t = tid; t < 4096; t += 256){
        int k = t >> 6, c = t & 63;
        W2s[k][c] = W2[k*64 + c];
    }
    __syncthreads();

    for (int t = tid; t < 4096; t += 256){
        int e = t >> 6, k = t & 63;
        int p = e >> 4;
        float h = g_P[(size_t)(base + p)*64 + k] + Vb[(size_t)sj[e]*64 + k];
        HT[k][e] = fmaxf(h, 0.f);
    }
    __syncthreads();

    int er = tid >> 4, cc = tid & 15;
    float acc[4][4] = {};
    #pragma unroll 8
    for (int k = 0; k < 64; k++){
        float4 h = *(const float4*)&HT [k][er << 2];
        float4 w = *(const float4*)&W2s[k][cc << 2];
        acc[0][0]+=h.x*w.x; acc[0][1]+=h.x*w.y; acc[0][2]+=h.x*w.z; acc[0][3]+=h.x*w.w;
        acc[1][0]+=h.y*w.x; acc[1][1]+=h.y*w.y; acc[1][2]+=h.y*w.z; acc[1][3]+=h.y*w.w;
        acc[2][0]+=h.z*w.x; acc[2][1]+=h.z*w.y; acc[2][2]+=h.z*w.z; acc[2][3]+=h.z*w.w;
        acc[3][0]+=h.w*w.x; acc[3][1]+=h.w*w.y; acc[3][2]+=h.w*w.z; acc[3][3]+=h.w*w.w;
    }
    #pragma unroll
    for (int c = 0; c < 4; c++){
        float m = fmaxf(fmaxf(acc[0][c], acc[1][c]), fmaxf(acc[2][c], acc[3][c]));
        red[er][(cc << 2) + c] = m;
    }
    __syncthreads();
    int p = tid >> 6, c = tid & 63;
    float m = red[4*p][c];
    m = fmaxf(m, red[4*p + 1][c]);
    m = fmaxf(m, red[4*p + 2][c]);
    m = fmaxf(m, red[4*p + 3][c]);
    Xout[(size_t)(base + p)*64 + c] = m + B2[c];
}

// ---------------- head stage 1: h1 = relu([X1|X2|X3] @ mw1 + mb1)  [64K x 192]@[192 x 128] ----------------
__global__ __launch_bounds__(256) void h1_kernel(const float* __restrict__ mw1,
                                                 const float* __restrict__ mb1){
    __shared__ __align__(16) float AT[64][68];
    __shared__ __align__(16) float WT[64][68];
    int p0 = blockIdx.y << 6;            // 64 points
    int c0 = blockIdx.x << 6;            // 64 of 128 output cols
    int tid = threadIdx.x;
    int er = tid >> 4, cc = tid & 15;

    float acc[4][4] = {};
    #pragma unroll
    for (int ch = 0; ch < 3; ch++){
        const float* src = (ch == 0) ? g_X1 : (ch == 1) ? g_X2 : g_X3;
        for (int t = tid; t < 4096; t += 256){
            int r = t >> 6, k = t & 63;
            AT[k][r] = src[(size_t)(p0 + r)*64 + k];
            WT[r][k] = mw1[(size_t)(ch*64 + r)*128 + c0 + k];   // WT[k_row][col]
        }
        __syncthreads();
        #pragma unroll 8
        for (int k = 0; k < 64; k++){
            float4 a = *(const float4*)&AT[k][er << 2];
            float4 w = *(const float4*)&WT[k][cc << 2];
            acc[0][0]+=a.x*w.x; acc[0][1]+=a.x*w.y; acc[0][2]+=a.x*w.z; acc[0][3]+=a.x*w.w;
            acc[1][0]+=a.y*w.x; acc[1][1]+=a.y*w.y; acc[1][2]+=a.y*w.z; acc[1][3]+=a.y*w.w;
            acc[2][0]+=a.z*w.x; acc[2][1]+=a.z*w.y; acc[2][2]+=a.z*w.z; acc[2][3]+=a.z*w.w;
            acc[3][0]+=a.w*w.x; acc[3][1]+=a.w*w.y; acc[3][2]+=a.w*w.z; acc[3][3]+=a.w*w.w;
        }
        __syncthreads();
    }
    #pragma unroll
    for (int r = 0; r < 4; r++){
        int row = p0 + (er << 2) + r;
        int cb  = c0 + (cc << 2);
        float4 o;
        o.x = fmaxf(acc[r][0] + mb1[cb + 0], 0.f);
        o.y = fmaxf(acc[r][1] + mb1[cb + 1], 0.f);
        o.z = fmaxf(acc[r][2] + mb1[cb + 2], 0.f);
        o.w = fmaxf(acc[r][3] + mb1[cb + 3], 0.f);
        *(float4*)&g_H1[(size_t)row*128 + cb] = o;
    }
}

// ---------------- head stage 2: h2 = relu(h1 @ mw2 + mb2) -> g_P  [64K x 128]@[128 x 64] ----------------
__global__ __launch_bounds__(256) void h2_kernel(const float* __restrict__ mw2,
                                                 const float* __restrict__ mb2){
    __shared__ __align__(16) float AT[64][68];
    __shared__ __align__(16) float WT[64][68];
    int p0 = blockIdx.x << 6;
    int tid = threadIdx.x;
    int er = tid >> 4, cc = tid & 15;

    float acc[4][4] = {};
    #pragma unroll
    for (int ch = 0; ch < 2; ch++){
        for (int t = tid; t < 4096; t += 256){
            int r = t >> 6, k = t & 63;
            AT[k][r] = g_H1[(size_t)(p0 + r)*128 + ch*64 + k];
            WT[r][k] = mw2[(size_t)(ch*64 + r)*64 + k];         // WT[k_row][col]
        }
        __syncthreads();
        #pragma unroll 8
        for (int k = 0; k < 64; k++){
            float4 a = *(const float4*)&AT[k][er << 2];
            float4 w = *(const float4*)&WT[k][cc << 2];
            acc[0][0]+=a.x*w.x; acc[0][1]+=a.x*w.y; acc[0][2]+=a.x*w.z; acc[0][3]+=a.x*w.w;
            acc[1][0]+=a.y*w.x; acc[1][1]+=a.y*w.y; acc[1][2]+=a.y*w.z; acc[1][3]+=a.y*w.w;
            acc[2][0]+=a.z*w.x; acc[2][1]+=a.z*w.y; acc[2][2]+=a.z*w.z; acc[2][3]+=a.z*w.w;
            acc[3][0]+=a.w*w.x; acc[3][1]+=a.w*w.y; acc[3][2]+=a.w*w.z; acc[3][3]+=a.w*w.w;
        }
        __syncthreads();
    }
    #pragma unroll
    for (int r = 0; r < 4; r++){
        int row = p0 + (er << 2) + r;
        int cb  = cc << 2;
        float4 o;
        o.x = fmaxf(acc[r][0] + mb2[cb + 0], 0.f);
        o.y = fmaxf(acc[r][1] + mb2[cb + 1], 0.f);
        o.z = fmaxf(acc[r][2] + mb2[cb + 2], 0.f);
        o.w = fmaxf(acc[r][3] + mb2[cb + 3], 0.f);
        *(float4*)&g_P[(size_t)row*64 + cb] = o;
    }
}

// ---------------- head stage 3+4 + log_softmax: warp per point ----------------
__global__ __launch_bounds__(256) void h34_kernel(const float* __restrict__ mw3, const float* __restrict__ mb3,
                                                  const float* __restrict__ mw4, const float* __restrict__ mb4,
                                                  float* __restrict__ out){
    __shared__ float h2s[8][64];
    int wid = threadIdx.x >> 5, lane = threadIdx.x & 31;
    int p = blockIdx.x*8 + wid;
    const float* row = g_P + (size_t)p*64;
    h2s[wid][lane]      = row[lane];
    h2s[wid][lane + 32] = row[lane + 32];
    __syncwarp();

    float a = mb3[lane];
    #pragma unroll 8
    for (int k = 0; k < 64; k++) a = fmaf(h2s[wid][k], mw3[k*32 + lane], a);
    a = fmaxf(a, 0.f);

    float q0 = a * mw4[lane*2 + 0];
    float q1 = a * mw4[lane*2 + 1];
    #pragma unroll
    for (int off = 16; off; off >>= 1){
        q0 += __shfl_down_sync(0xffffffffu, q0, off);
        q1 += __shfl_down_sync(0xffffffffu, q1, off);
    }
    if (lane == 0){
        float o0 = q0 + mb4[0], o1 = q1 + mb4[1];
        float m   = fmaxf(o0, o1);
        float lse = m + logf(expf(o0 - m) + expf(o1 - m));
        out[(size_t)p*2 + 0] = o0 - lse;
        out[(size_t)p*2 + 1] = o1 - lse;
    }
}

// ---------------- launch ----------------
extern "C" void kernel_launch(void* const* d_in, const int* in_sizes, int n_in,
                              void* d_out, int out_size){
    const float* x    = (const float*)d_in[0];
    const float* c1w1 = (const float*)d_in[1];
    const float* c1b1 = (const float*)d_in[2];
    const float* c1w2 = (const float*)d_in[3];
    const float* c1b2 = (const float*)d_in[4];
    const float* c2w1 = (const float*)d_in[5];
    const float* c2b1 = (const float*)d_in[6];
    const float* c2w2 = (const float*)d_in[7];
    const float* c2b2 = (const float*)d_in[8];
    const float* c3w1 = (const float*)d_in[9];
    const float* c3b1 = (const float*)d_in[10];
    const float* c3w2 = (const float*)d_in[11];
    const float* c3b2 = (const float*)d_in[12];
    const float* mw1  = (const float*)d_in[13];
    const float* mb1  = (const float*)d_in[14];
    const float* mw2  = (const float*)d_in[15];
    const float* mb2  = (const float*)d_in[16];
    const float* mw3  = (const float*)d_in[17];
    const float* mb3  = (const float*)d_in[18];
    const float* mw4  = (const float*)d_in[19];
    const float* mb4  = (const float*)d_in[20];

    void *pX1, *pX2, *pX3;
    cudaGetSymbolAddress(&pX1, g_X1);
    cudaGetSymbolAddress(&pX2, g_X2);
    cudaGetSymbolAddress(&pX3, g_X3);
    float* X1 = (float*)pX1;
    float* X2 = (float*)pX2;
    float* X3 = (float*)pX3;

    // ---- layer 1 (Cin = 1): fused knn ----
    knn1_kernel<<<dim3(16, BB), 256>>>(x);
    pv_kernel  <<<16384, 256>>>(x, c1w1, c1b1, 1);
    edge_kernel<<<16384, 256>>>(c1w2, c1b2, X1);

    // ---- layer 2 (Cin = 64) ----
    sq_kernel  <<<8192, 256>>>(X1);
    knnC_kernel<<<dim3(16, BB), 256>>>(X1);
    pv_kernel  <<<16384, 256>>>(X1, c2w1, c2b1, 64);
    edge_kernel<<<16384, 256>>>(c2w2, c2b2, X2);

    // ---- layer 3 (Cin = 64) ----
    sq_kernel  <<<8192, 256>>>(X2);
    knnC_kernel<<<dim3(16, BB), 256>>>(X2);
    pv_kernel  <<<16384, 256>>>(X2, c3w1, c3b1, 64);
    edge_kernel<<<16384, 256>>>(c3w2, c3b2, X3);

    // ---- head: tiled GEMM chain ----
    h1_kernel <<<dim3(2, 1024), 256>>>(mw1, mb1);
    h2_kernel <<<1024, 256>>>(mw2, mb2);
    h34_kernel<<<8192, 256>>>(mw3, mb3, mw4, mb4, (float*)d_out);
}